// round 9
// baseline (speedup 1.0000x reference)
#include <cuda_runtime.h>
#include <cuda_bf16.h>
#include <math.h>

// ---------------------------------------------------------------------------
// PatchQuantumGenerator: 5 qubits, 1 ancilla, 4 StronglyEntanglingLayers,
// 4 generators.
//   * circuit after RY-embedding = fixed 32x32 unitary U_g per generator
//   * embedded state is a real product state s[j]
//   * p0/max(p0) == probs[:16]/max(probs[:16])  (sum normalization cancels)
// => out[b, g*16+i] = |y_i|^2 / max_i |y_i|^2,  y = U_g[0:16,:] @ s(b)
// Kernel B: packed fp32x2 FMA, 1 elem/thread (low regs, high occupancy),
// generator-split blocks, v[] generated on the fly from p4[16].
// ---------------------------------------------------------------------------

#define NQ 5
#define DIM 32
#define NOUT 16
#define G 4
#define L 4
#define NGATES (L * NQ)

// W layout: [g][j=input basis 0..31][c], c<16: Re U[c][j], c>=16: Im U[c][j]
__device__ float g_W[G][DIM][2 * NOUT];

typedef unsigned long long ull;

__device__ __forceinline__ ull ffma2(ull a, ull b, ull c) {
    ull d;
    asm("fma.rn.f32x2 %0, %1, %2, %3;" : "=l"(d) : "l"(a), "l"(b), "l"(c));
    return d;
}
__device__ __forceinline__ ull pack2(float x) {
    ull r;
    asm("mov.b64 %0, {%1, %1};" : "=l"(r) : "f"(x));
    return r;
}
__device__ __forceinline__ float2 unpack2(ull a) {
    float lo, hi;
    asm("mov.b64 {%0, %1}, %2;" : "=f"(lo), "=f"(hi) : "l"(a));
    return make_float2(lo, hi);
}

// ---------------------------------------------------------------------------
// Kernel A: build the 4 unitaries. One block per generator, 512 threads:
// thread = (col = t>>4, p = t&15). All 16 threads of a column sit in ONE
// warp (warp = 2 columns), so per-gate sync is __syncwarp, not block-wide.
// ---------------------------------------------------------------------------
__global__ void __launch_bounds__(512, 1)
build_unitaries_kernel(const float* __restrict__ w) {
    __shared__ float2 S[DIM][DIM];        // [column][amplitude], 8KB
    __shared__ float gm[NGATES][8];       // gate matrices

    const int g   = blockIdx.x;
    const int t   = threadIdx.x;          // 0..511
    const int col = t >> 4;               // 0..31
    const int p   = t & 15;               // pair index 0..15

    if (t < NGATES) {
        const int l = t / NQ, q = t % NQ;
        const float phi   = w[((g * L + l) * NQ + q) * 3 + 0];
        const float theta = w[((g * L + l) * NQ + q) * 3 + 1];
        const float omega = w[((g * L + l) * NQ + q) * 3 + 2];
        const float c = cosf(0.5f * theta);
        const float s = sinf(0.5f * theta);
        float epx, epy, emx, emy;
        sincosf(-0.5f * (phi + omega), &epy, &epx);   // ep = e^{-i(phi+omega)/2}
        sincosf(-0.5f * (phi - omega), &emy, &emx);   // em = e^{-i(phi-omega)/2}
        // m00 = ep*c ; m01 = -conj(em)*s ; m10 = em*s ; m11 = conj(ep)*c
        gm[t][0] = epx * c;   gm[t][1] = epy * c;
        gm[t][2] = -emx * s;  gm[t][3] = emy * s;
        gm[t][4] = emx * s;   gm[t][5] = emy * s;
        gm[t][6] = epx * c;   gm[t][7] = -epy * c;
    }

    S[col][p]      = make_float2(col == p      ? 1.0f : 0.0f, 0.0f);
    S[col][p + 16] = make_float2(col == p + 16 ? 1.0f : 0.0f, 0.0f);
    __syncthreads();

    float2* a = S[col];

    for (int l = 0; l < L; ++l) {
        for (int q = 0; q < NQ; ++q) {
            const float* m = gm[l * NQ + q];
            const int msk = 1 << (4 - q);
            const int lo  = p & (msk - 1);
            const int i0  = ((p & ~(msk - 1)) << 1) | lo;
            const int i1  = i0 | msk;
            const float2 a0 = a[i0], a1 = a[i1];
            float2 n0, n1;
            n0.x = m[0] * a0.x - m[1] * a0.y + m[2] * a1.x - m[3] * a1.y;
            n0.y = m[0] * a0.y + m[1] * a0.x + m[2] * a1.y + m[3] * a1.x;
            n1.x = m[4] * a0.x - m[5] * a0.y + m[6] * a1.x - m[7] * a1.y;
            n1.y = m[4] * a0.y + m[5] * a0.x + m[6] * a1.y + m[7] * a1.x;
            a[i0] = n0;
            a[i1] = n1;
            __syncwarp();
        }
        const int r = (l % (NQ - 1)) + 1;
        for (int q = 0; q < NQ; ++q) {
            const int cm = 1 << (4 - q);
            const int tq = (q + r) % NQ;
            const int tm = 1 << (4 - tq);
            const int lo = p & (tm - 1);
            const int i0 = ((p & ~(tm - 1)) << 1) | lo;   // target bit = 0
            if (i0 & cm) {
                const int i1 = i0 | tm;
                const float2 tmp = a[i0];
                a[i0] = a[i1];
                a[i1] = tmp;
            }
            __syncwarp();
        }
    }

    g_W[g][col][p]        = a[p].x;
    g_W[g][col][NOUT + p] = a[p].y;
}

// ---------------------------------------------------------------------------
// Kernel B: generator-split. Block = (tile of 128 batch elems) x (one g).
// 128 threads, 1 element/thread, packed f32x2 accumulators, v on the fly.
// ---------------------------------------------------------------------------
__global__ void __launch_bounds__(128)
qgen_main_kernel(const float* __restrict__ x, float* __restrict__ out, int B) {
    __shared__ float Wsh[DIM][2 * NOUT];   // 4 KB, this block's generator only
    const int gsel = blockIdx.x & 3;
    const int tile = blockIdx.x >> 2;

    {
        // 4 KB tile = 256 float4; 128 threads -> 2 float4 each
        const float4* src = reinterpret_cast<const float4*>(&g_W[gsel][0][0]);
        float4* dst = reinterpret_cast<float4*>(&Wsh[0][0]);
        dst[threadIdx.x]       = src[threadIdx.x];
        dst[threadIdx.x + 128] = src[threadIdx.x + 128];
    }
    __syncthreads();

    const int b = tile * 128 + threadIdx.x;
    if (b >= B) return;

    // --- product-state factors: p4[16] over qubits 0..3, (c4,s4) for qubit 4
    float p4[16], c4, s4;
    {
        float cc[NQ], ss[NQ];
        #pragma unroll
        for (int q = 0; q < NQ; ++q)
            __sincosf(0.5f * x[b * NQ + q], &ss[q], &cc[q]);
        float p2[4], p3[8];
        #pragma unroll
        for (int k = 0; k < 4; ++k)  p2[k] = ((k >> 1) ? ss[0] : cc[0]) * ((k & 1) ? ss[1] : cc[1]);
        #pragma unroll
        for (int k = 0; k < 8; ++k)  p3[k] = p2[k >> 1] * ((k & 1) ? ss[2] : cc[2]);
        #pragma unroll
        for (int k = 0; k < 16; ++k) p4[k] = p3[k >> 1] * ((k & 1) ? ss[3] : cc[3]);
        c4 = cc[4]; s4 = ss[4];
    }

    // acc[u] packs columns (2u, 2u+1); u<8 -> Re pairs, u>=8 -> Im pairs
    ull acc[NOUT];
    #pragma unroll
    for (int u = 0; u < NOUT; ++u) acc[u] = 0ULL;

    #pragma unroll
    for (int j4 = 0; j4 < 16; ++j4) {
        // v[2*j4] = p4[j4]*c4 ; v[2*j4+1] = p4[j4]*s4
        const ull sjA = pack2(p4[j4] * c4);
        const ull sjB = pack2(p4[j4] * s4);
        const ulonglong2* rowA = reinterpret_cast<const ulonglong2*>(&Wsh[2 * j4][0]);
        const ulonglong2* rowB = reinterpret_cast<const ulonglong2*>(&Wsh[2 * j4 + 1][0]);
        #pragma unroll
        for (int k2 = 0; k2 < 8; ++k2) {
            const ulonglong2 wA = rowA[k2];   // broadcast LDS.128
            acc[2 * k2 + 0] = ffma2(wA.x, sjA, acc[2 * k2 + 0]);
            acc[2 * k2 + 1] = ffma2(wA.y, sjA, acc[2 * k2 + 1]);
        }
        #pragma unroll
        for (int k2 = 0; k2 < 8; ++k2) {
            const ulonglong2 wB = rowB[k2];
            acc[2 * k2 + 0] = ffma2(wB.x, sjB, acc[2 * k2 + 0]);
            acc[2 * k2 + 1] = ffma2(wB.y, sjB, acc[2 * k2 + 1]);
        }
    }

    // epilogue: probs, max, normalize, store 16 floats
    float pr[NOUT];
    float mx = 0.0f;
    #pragma unroll
    for (int k = 0; k < 8; ++k) {
        const float2 re = unpack2(acc[k]);        // cols 2k, 2k+1 (Re)
        const float2 im = unpack2(acc[8 + k]);    // cols 16+2k, 16+2k+1 (Im)
        pr[2 * k + 0] = re.x * re.x + im.x * im.x;
        pr[2 * k + 1] = re.y * re.y + im.y * im.y;
        mx = fmaxf(mx, fmaxf(pr[2 * k], pr[2 * k + 1]));
    }
    const float inv = 1.0f / mx;
    float4* ov = reinterpret_cast<float4*>(out + (size_t)b * (G * NOUT) + gsel * NOUT);
    #pragma unroll
    for (int i4 = 0; i4 < 4; ++i4) {
        float4 o;
        o.x = pr[i4 * 4 + 0] * inv;
        o.y = pr[i4 * 4 + 1] * inv;
        o.z = pr[i4 * 4 + 2] * inv;
        o.w = pr[i4 * 4 + 3] * inv;
        ov[i4] = o;
    }
}

extern "C" void kernel_launch(void* const* d_in, const int* in_sizes, int n_in,
                              void* d_out, int out_size) {
    const float* x = (const float*)d_in[0];        // [B, 5]
    const float* w = (const float*)d_in[1];        // [4, 4, 5, 3]
    float* out = (float*)d_out;                    // [B, 64]
    const int B = in_sizes[0] / NQ;

    build_unitaries_kernel<<<G, 512>>>(w);
    const int tiles = (B + 127) / 128;             // 1 element per thread
    qgen_main_kernel<<<tiles * G, 128>>>(x, out, B);
}

// round 10
// speedup vs baseline: 1.2412x; 1.2412x over previous
#include <cuda_runtime.h>
#include <cuda_bf16.h>
#include <math.h>

// ---------------------------------------------------------------------------
// PatchQuantumGenerator: 5 qubits, 1 ancilla, 4 StronglyEntanglingLayers,
// 4 generators.
//   * circuit after RY-embedding = fixed 32x32 unitary U_g per generator
//   * embedded state is a real product state s[j]
//   * p0/max(p0) == probs[:16]/max(probs[:16])  (sum normalization cancels)
// => out[b, g*16+i] = |y_i|^2 / max_i |y_i|^2,  y = U_g[0:16,:] @ s(b)
// Kernel B: packed fp32x2 FMA, 2 elems/thread (LDS amortized), output
// columns split across thread pairs (halved accumulators -> more warps).
// ---------------------------------------------------------------------------

#define NQ 5
#define DIM 32
#define NOUT 16
#define G 4
#define L 4
#define NGATES (L * NQ)

// W layout per row j: [Re(0..7), Im(0..7), Re(8..15), Im(8..15)]
// -> half h occupies floats [16h, 16h+16): its 8 Re then its 8 Im.
__device__ float g_W[G][DIM][2 * NOUT];

typedef unsigned long long ull;

__device__ __forceinline__ ull ffma2(ull a, ull b, ull c) {
    ull d;
    asm("fma.rn.f32x2 %0, %1, %2, %3;" : "=l"(d) : "l"(a), "l"(b), "l"(c));
    return d;
}
__device__ __forceinline__ ull pack2(float x) {
    ull r;
    asm("mov.b64 %0, {%1, %1};" : "=l"(r) : "f"(x));
    return r;
}
__device__ __forceinline__ float2 unpack2(ull a) {
    float lo, hi;
    asm("mov.b64 {%0, %1}, %2;" : "=f"(lo), "=f"(hi) : "l"(a));
    return make_float2(lo, hi);
}

// ---------------------------------------------------------------------------
// Kernel A: build the 4 unitaries. One block per generator, 512 threads:
// thread = (col = t>>4, p = t&15); per-gate sync is warp-local.
// ---------------------------------------------------------------------------
__global__ void __launch_bounds__(512, 1)
build_unitaries_kernel(const float* __restrict__ w) {
    __shared__ float2 S[DIM][DIM];        // [column][amplitude], 8KB
    __shared__ float gm[NGATES][8];       // gate matrices

    const int g   = blockIdx.x;
    const int t   = threadIdx.x;          // 0..511
    const int col = t >> 4;               // 0..31
    const int p   = t & 15;               // pair index 0..15

    if (t < NGATES) {
        const int l = t / NQ, q = t % NQ;
        const float phi   = w[((g * L + l) * NQ + q) * 3 + 0];
        const float theta = w[((g * L + l) * NQ + q) * 3 + 1];
        const float omega = w[((g * L + l) * NQ + q) * 3 + 2];
        const float c = cosf(0.5f * theta);
        const float s = sinf(0.5f * theta);
        float epx, epy, emx, emy;
        sincosf(-0.5f * (phi + omega), &epy, &epx);   // ep = e^{-i(phi+omega)/2}
        sincosf(-0.5f * (phi - omega), &emy, &emx);   // em = e^{-i(phi-omega)/2}
        // m00 = ep*c ; m01 = -conj(em)*s ; m10 = em*s ; m11 = conj(ep)*c
        gm[t][0] = epx * c;   gm[t][1] = epy * c;
        gm[t][2] = -emx * s;  gm[t][3] = emy * s;
        gm[t][4] = emx * s;   gm[t][5] = emy * s;
        gm[t][6] = epx * c;   gm[t][7] = -epy * c;
    }

    S[col][p]      = make_float2(col == p      ? 1.0f : 0.0f, 0.0f);
    S[col][p + 16] = make_float2(col == p + 16 ? 1.0f : 0.0f, 0.0f);
    __syncthreads();

    float2* a = S[col];

    for (int l = 0; l < L; ++l) {
        for (int q = 0; q < NQ; ++q) {
            const float* m = gm[l * NQ + q];
            const int msk = 1 << (4 - q);
            const int lo  = p & (msk - 1);
            const int i0  = ((p & ~(msk - 1)) << 1) | lo;
            const int i1  = i0 | msk;
            const float2 a0 = a[i0], a1 = a[i1];
            float2 n0, n1;
            n0.x = m[0] * a0.x - m[1] * a0.y + m[2] * a1.x - m[3] * a1.y;
            n0.y = m[0] * a0.y + m[1] * a0.x + m[2] * a1.y + m[3] * a1.x;
            n1.x = m[4] * a0.x - m[5] * a0.y + m[6] * a1.x - m[7] * a1.y;
            n1.y = m[4] * a0.y + m[5] * a0.x + m[6] * a1.y + m[7] * a1.x;
            a[i0] = n0;
            a[i1] = n1;
            __syncwarp();
        }
        const int r = (l % (NQ - 1)) + 1;
        for (int q = 0; q < NQ; ++q) {
            const int cm = 1 << (4 - q);
            const int tq = (q + r) % NQ;
            const int tm = 1 << (4 - tq);
            const int lo = p & (tm - 1);
            const int i0 = ((p & ~(tm - 1)) << 1) | lo;   // target bit = 0
            if (i0 & cm) {
                const int i1 = i0 | tm;
                const float2 tmp = a[i0];
                a[i0] = a[i1];
                a[i1] = tmp;
            }
            __syncwarp();
        }
    }

    // output i = p: Re -> col (i>>3)*16 + (i&7), Im -> +8
    const int h  = p >> 3;
    const int i7 = p & 7;
    g_W[g][col][h * 16 + i7]     = a[p].x;
    g_W[g][col][h * 16 + 8 + i7] = a[p].y;
}

// ---------------------------------------------------------------------------
// Kernel B: block = (tile of 128 batch elems) x (one g). 128 threads.
// Thread = (idx = tid>>1 -> elems b0,b0+64 ; h = tid&1 -> col half).
// ---------------------------------------------------------------------------
__global__ void __launch_bounds__(128, 5)
qgen_main_kernel(const float* __restrict__ x, float* __restrict__ out, int B) {
    __shared__ float Wsh[DIM][2 * NOUT];   // 4 KB
    const int gsel = blockIdx.x & 3;
    const int tile = blockIdx.x >> 2;

    {
        // 4 KB = 256 float4; 128 threads -> 2 each
        const float4* src = reinterpret_cast<const float4*>(&g_W[gsel][0][0]);
        float4* dst = reinterpret_cast<float4*>(&Wsh[0][0]);
        dst[threadIdx.x]       = src[threadIdx.x];
        dst[threadIdx.x + 128] = src[threadIdx.x + 128];
    }
    __syncthreads();

    const int h   = threadIdx.x & 1;       // column half
    const int idx = threadIdx.x >> 1;      // 0..63
    const int b0  = tile * 128 + idx;
    const int b1  = b0 + 64;
    if (b1 >= B + 64) return;              // B multiple of 128 in practice

    // product-state factors per element: p4[16] (qubits 0..3) + (c4,s4)
    float p40[16], c40, s40, p41[16], c41, s41;
    {
        float cc[NQ], ss[NQ];
        #pragma unroll
        for (int q = 0; q < NQ; ++q)
            __sincosf(0.5f * x[b0 * NQ + q], &ss[q], &cc[q]);
        float p2[4], p3[8];
        #pragma unroll
        for (int k = 0; k < 4; ++k)  p2[k] = ((k >> 1) ? ss[0] : cc[0]) * ((k & 1) ? ss[1] : cc[1]);
        #pragma unroll
        for (int k = 0; k < 8; ++k)  p3[k] = p2[k >> 1] * ((k & 1) ? ss[2] : cc[2]);
        #pragma unroll
        for (int k = 0; k < 16; ++k) p40[k] = p3[k >> 1] * ((k & 1) ? ss[3] : cc[3]);
        c40 = cc[4]; s40 = ss[4];
    }
    {
        float cc[NQ], ss[NQ];
        #pragma unroll
        for (int q = 0; q < NQ; ++q)
            __sincosf(0.5f * x[b1 * NQ + q], &ss[q], &cc[q]);
        float p2[4], p3[8];
        #pragma unroll
        for (int k = 0; k < 4; ++k)  p2[k] = ((k >> 1) ? ss[0] : cc[0]) * ((k & 1) ? ss[1] : cc[1]);
        #pragma unroll
        for (int k = 0; k < 8; ++k)  p3[k] = p2[k >> 1] * ((k & 1) ? ss[2] : cc[2]);
        #pragma unroll
        for (int k = 0; k < 16; ++k) p41[k] = p3[k >> 1] * ((k & 1) ? ss[3] : cc[3]);
        c41 = cc[4]; s41 = ss[4];
    }

    // acc layout (per element, this col-half): k<4 Re pairs, k>=4 Im pairs
    ull a0[8], a1[8];
    #pragma unroll
    for (int k = 0; k < 8; ++k) { a0[k] = 0ULL; a1[k] = 0ULL; }

    const int hoff = h * 16;   // float offset of this half within a row

    #pragma unroll
    for (int j4 = 0; j4 < 16; ++j4) {
        // v[2*j4] = p4*c4 ; v[2*j4+1] = p4*s4
        const ull sA0 = pack2(p40[j4] * c40);
        const ull sB0 = pack2(p40[j4] * s40);
        const ull sA1 = pack2(p41[j4] * c41);
        const ull sB1 = pack2(p41[j4] * s41);
        const ulonglong2* rA = reinterpret_cast<const ulonglong2*>(&Wsh[2 * j4][hoff]);
        const ulonglong2* rB = reinterpret_cast<const ulonglong2*>(&Wsh[2 * j4 + 1][hoff]);
        {
            const ulonglong2 w0 = rA[0], w1 = rA[1], w2 = rA[2], w3 = rA[3];
            a0[0] = ffma2(w0.x, sA0, a0[0]); a0[1] = ffma2(w0.y, sA0, a0[1]);
            a0[2] = ffma2(w1.x, sA0, a0[2]); a0[3] = ffma2(w1.y, sA0, a0[3]);
            a0[4] = ffma2(w2.x, sA0, a0[4]); a0[5] = ffma2(w2.y, sA0, a0[5]);
            a0[6] = ffma2(w3.x, sA0, a0[6]); a0[7] = ffma2(w3.y, sA0, a0[7]);
            a1[0] = ffma2(w0.x, sA1, a1[0]); a1[1] = ffma2(w0.y, sA1, a1[1]);
            a1[2] = ffma2(w1.x, sA1, a1[2]); a1[3] = ffma2(w1.y, sA1, a1[3]);
            a1[4] = ffma2(w2.x, sA1, a1[4]); a1[5] = ffma2(w2.y, sA1, a1[5]);
            a1[6] = ffma2(w3.x, sA1, a1[6]); a1[7] = ffma2(w3.y, sA1, a1[7]);
        }
        {
            const ulonglong2 w0 = rB[0], w1 = rB[1], w2 = rB[2], w3 = rB[3];
            a0[0] = ffma2(w0.x, sB0, a0[0]); a0[1] = ffma2(w0.y, sB0, a0[1]);
            a0[2] = ffma2(w1.x, sB0, a0[2]); a0[3] = ffma2(w1.y, sB0, a0[3]);
            a0[4] = ffma2(w2.x, sB0, a0[4]); a0[5] = ffma2(w2.y, sB0, a0[5]);
            a0[6] = ffma2(w3.x, sB0, a0[6]); a0[7] = ffma2(w3.y, sB0, a0[7]);
            a1[0] = ffma2(w0.x, sB1, a1[0]); a1[1] = ffma2(w0.y, sB1, a1[1]);
            a1[2] = ffma2(w1.x, sB1, a1[2]); a1[3] = ffma2(w1.y, sB1, a1[3]);
            a1[4] = ffma2(w2.x, sB1, a1[4]); a1[5] = ffma2(w2.y, sB1, a1[5]);
            a1[6] = ffma2(w3.x, sB1, a1[6]); a1[7] = ffma2(w3.y, sB1, a1[7]);
        }
    }

    // epilogue: this thread covers outputs 8h..8h+7 of its two elements;
    // max over all 16 outputs combined with partner lane via shfl.xor(1).
    #pragma unroll
    for (int e = 0; e < 2; ++e) {
        const ull* a = e ? a1 : a0;
        const int b = e ? b1 : b0;
        float pr[8];
        float mx = 0.0f;
        #pragma unroll
        for (int k = 0; k < 4; ++k) {
            const float2 re = unpack2(a[k]);       // outputs 8h+2k, 8h+2k+1
            const float2 im = unpack2(a[4 + k]);
            pr[2 * k + 0] = re.x * re.x + im.x * im.x;
            pr[2 * k + 1] = re.y * re.y + im.y * im.y;
            mx = fmaxf(mx, fmaxf(pr[2 * k], pr[2 * k + 1]));
        }
        mx = fmaxf(mx, __shfl_xor_sync(0xffffffffu, mx, 1));
        const float inv = 1.0f / mx;
        float4* ov = reinterpret_cast<float4*>(out + (size_t)b * (G * NOUT) + gsel * NOUT + 8 * h);
        #pragma unroll
        for (int i4 = 0; i4 < 2; ++i4) {
            float4 o;
            o.x = pr[i4 * 4 + 0] * inv;
            o.y = pr[i4 * 4 + 1] * inv;
            o.z = pr[i4 * 4 + 2] * inv;
            o.w = pr[i4 * 4 + 3] * inv;
            ov[i4] = o;
        }
    }
}

extern "C" void kernel_launch(void* const* d_in, const int* in_sizes, int n_in,
                              void* d_out, int out_size) {
    const float* x = (const float*)d_in[0];        // [B, 5]
    const float* w = (const float*)d_in[1];        // [4, 4, 5, 3]
    float* out = (float*)d_out;                    // [B, 64]
    const int B = in_sizes[0] / NQ;

    build_unitaries_kernel<<<G, 512>>>(w);
    const int tiles = (B + 127) / 128;             // 128 elements per tile
    qgen_main_kernel<<<tiles * G, 128>>>(x, out, B);
}

// round 11
// speedup vs baseline: 1.2538x; 1.0102x over previous
#include <cuda_runtime.h>
#include <cuda_bf16.h>
#include <math.h>

// ---------------------------------------------------------------------------
// PatchQuantumGenerator: 5 qubits, 1 ancilla, 4 StronglyEntanglingLayers,
// 4 generators.
//   * circuit after RY-embedding = fixed 32x32 unitary U_g per generator
//   * embedded state is a real product state s[j]
//   * p0/max(p0) == probs[:16]/max(probs[:16])  (sum normalization cancels)
// => out[b, g*16+i] = |y_i|^2 / max_i |y_i|^2,  y = U_g[0:16,:] @ s(b)
// Kernel B: packed fp32x2 FMA, 2 elems/thread, output columns split across
// thread pairs; p-prefix kept to p3 (reg trim) -> 6 blocks/SM.
// ---------------------------------------------------------------------------

#define NQ 5
#define DIM 32
#define NOUT 16
#define G 4
#define L 4
#define NGATES (L * NQ)

// W layout per row j: [Re(0..7), Im(0..7), Re(8..15), Im(8..15)]
// -> half h occupies floats [16h, 16h+16): its 8 Re then its 8 Im.
__device__ float g_W[G][DIM][2 * NOUT];

typedef unsigned long long ull;

__device__ __forceinline__ ull ffma2(ull a, ull b, ull c) {
    ull d;
    asm("fma.rn.f32x2 %0, %1, %2, %3;" : "=l"(d) : "l"(a), "l"(b), "l"(c));
    return d;
}
__device__ __forceinline__ ull fmul2(ull a, ull b) {
    ull d;
    asm("mul.rn.f32x2 %0, %1, %2;" : "=l"(d) : "l"(a), "l"(b));
    return d;
}
__device__ __forceinline__ ull packab(float lo, float hi) {
    ull r;
    asm("mov.b64 %0, {%1, %2};" : "=l"(r) : "f"(lo), "f"(hi));
    return r;
}
__device__ __forceinline__ ull pack2(float x) {
    ull r;
    asm("mov.b64 %0, {%1, %1};" : "=l"(r) : "f"(x));
    return r;
}
__device__ __forceinline__ float2 unpack2(ull a) {
    float lo, hi;
    asm("mov.b64 {%0, %1}, %2;" : "=f"(lo), "=f"(hi) : "l"(a));
    return make_float2(lo, hi);
}

// ---------------------------------------------------------------------------
// Kernel A: build the 4 unitaries. One block per generator, 512 threads:
// thread = (col = t>>4, p = t&15); per-gate sync is warp-local.
// ---------------------------------------------------------------------------
__global__ void __launch_bounds__(512, 1)
build_unitaries_kernel(const float* __restrict__ w) {
    __shared__ float2 S[DIM][DIM];        // [column][amplitude], 8KB
    __shared__ float gm[NGATES][8];       // gate matrices

    const int g   = blockIdx.x;
    const int t   = threadIdx.x;          // 0..511
    const int col = t >> 4;               // 0..31
    const int p   = t & 15;               // pair index 0..15

    if (t < NGATES) {
        const int l = t / NQ, q = t % NQ;
        const float phi   = w[((g * L + l) * NQ + q) * 3 + 0];
        const float theta = w[((g * L + l) * NQ + q) * 3 + 1];
        const float omega = w[((g * L + l) * NQ + q) * 3 + 2];
        const float c = cosf(0.5f * theta);
        const float s = sinf(0.5f * theta);
        float epx, epy, emx, emy;
        sincosf(-0.5f * (phi + omega), &epy, &epx);   // ep = e^{-i(phi+omega)/2}
        sincosf(-0.5f * (phi - omega), &emy, &emx);   // em = e^{-i(phi-omega)/2}
        // m00 = ep*c ; m01 = -conj(em)*s ; m10 = em*s ; m11 = conj(ep)*c
        gm[t][0] = epx * c;   gm[t][1] = epy * c;
        gm[t][2] = -emx * s;  gm[t][3] = emy * s;
        gm[t][4] = emx * s;   gm[t][5] = emy * s;
        gm[t][6] = epx * c;   gm[t][7] = -epy * c;
    }

    S[col][p]      = make_float2(col == p      ? 1.0f : 0.0f, 0.0f);
    S[col][p + 16] = make_float2(col == p + 16 ? 1.0f : 0.0f, 0.0f);
    __syncthreads();

    float2* a = S[col];

    for (int l = 0; l < L; ++l) {
        for (int q = 0; q < NQ; ++q) {
            const float* m = gm[l * NQ + q];
            const int msk = 1 << (4 - q);
            const int lo  = p & (msk - 1);
            const int i0  = ((p & ~(msk - 1)) << 1) | lo;
            const int i1  = i0 | msk;
            const float2 a0 = a[i0], a1 = a[i1];
            float2 n0, n1;
            n0.x = m[0] * a0.x - m[1] * a0.y + m[2] * a1.x - m[3] * a1.y;
            n0.y = m[0] * a0.y + m[1] * a0.x + m[2] * a1.y + m[3] * a1.x;
            n1.x = m[4] * a0.x - m[5] * a0.y + m[6] * a1.x - m[7] * a1.y;
            n1.y = m[4] * a0.y + m[5] * a0.x + m[6] * a1.y + m[7] * a1.x;
            a[i0] = n0;
            a[i1] = n1;
            __syncwarp();
        }
        const int r = (l % (NQ - 1)) + 1;
        for (int q = 0; q < NQ; ++q) {
            const int cm = 1 << (4 - q);
            const int tq = (q + r) % NQ;
            const int tm = 1 << (4 - tq);
            const int lo = p & (tm - 1);
            const int i0 = ((p & ~(tm - 1)) << 1) | lo;   // target bit = 0
            if (i0 & cm) {
                const int i1 = i0 | tm;
                const float2 tmp = a[i0];
                a[i0] = a[i1];
                a[i1] = tmp;
            }
            __syncwarp();
        }
    }

    // output i = p: Re -> col (i>>3)*16 + (i&7), Im -> +8
    const int h  = p >> 3;
    const int i7 = p & 7;
    g_W[g][col][h * 16 + i7]     = a[p].x;
    g_W[g][col][h * 16 + 8 + i7] = a[p].y;
}

// ---------------------------------------------------------------------------
// Kernel B: block = (tile of 128 batch elems) x (one g). 128 threads.
// Thread = (idx = tid>>1 -> elems b0,b0+64 ; h = tid&1 -> col half).
// Element pair packed in f32x2 prologue; prefix kept to p3 (reg trim).
// ---------------------------------------------------------------------------
__global__ void __launch_bounds__(128, 6)
qgen_main_kernel(const float* __restrict__ x, float* __restrict__ out, int B) {
    __shared__ float Wsh[DIM][2 * NOUT];   // 4 KB
    const int gsel = blockIdx.x & 3;
    const int tile = blockIdx.x >> 2;

    {
        // 4 KB = 256 float4; 128 threads -> 2 each
        const float4* src = reinterpret_cast<const float4*>(&g_W[gsel][0][0]);
        float4* dst = reinterpret_cast<float4*>(&Wsh[0][0]);
        dst[threadIdx.x]       = src[threadIdx.x];
        dst[threadIdx.x + 128] = src[threadIdx.x + 128];
    }
    __syncthreads();

    const int h   = threadIdx.x & 1;       // column half
    const int idx = threadIdx.x >> 1;      // 0..63
    const int b0  = tile * 128 + idx;
    const int b1  = b0 + 64;
    if (b1 >= B + 64) return;              // B multiple of 128 in practice

    // packed (elem0, elem1) product-state prefix up to qubit 3: p3p[8];
    // qubit-3 and qubit-4 factors kept as packed pairs.
    ull p3p[8], c3p, s3p, c4p, s4p;
    {
        float cc0[NQ], ss0[NQ], cc1[NQ], ss1[NQ];
        #pragma unroll
        for (int q = 0; q < NQ; ++q) {
            __sincosf(0.5f * x[b0 * NQ + q], &ss0[q], &cc0[q]);
            __sincosf(0.5f * x[b1 * NQ + q], &ss1[q], &cc1[q]);
        }
        ull f0c = packab(cc0[0], cc1[0]), f0s = packab(ss0[0], ss1[0]);
        ull f1c = packab(cc0[1], cc1[1]), f1s = packab(ss0[1], ss1[1]);
        ull f2c = packab(cc0[2], cc1[2]), f2s = packab(ss0[2], ss1[2]);
        c3p = packab(cc0[3], cc1[3]);  s3p = packab(ss0[3], ss1[3]);
        c4p = packab(cc0[4], cc1[4]);  s4p = packab(ss0[4], ss1[4]);
        ull p2p[4];
        p2p[0] = fmul2(f0c, f1c); p2p[1] = fmul2(f0c, f1s);
        p2p[2] = fmul2(f0s, f1c); p2p[3] = fmul2(f0s, f1s);
        #pragma unroll
        for (int k = 0; k < 4; ++k) {
            p3p[2 * k + 0] = fmul2(p2p[k], f2c);
            p3p[2 * k + 1] = fmul2(p2p[k], f2s);
        }
    }

    // acc layout (per element, this col-half): k<4 Re pairs, k>=4 Im pairs
    ull a0[8], a1[8];
    #pragma unroll
    for (int k = 0; k < 8; ++k) { a0[k] = 0ULL; a1[k] = 0ULL; }

    const int hoff = h * 16;   // float offset of this half within a row

    #pragma unroll
    for (int j4 = 0; j4 < 16; ++j4) {
        // p4 = p3[j4>>1] * (j4&1 ? s3 : c3); vA = p4*c4, vB = p4*s4 (packed)
        const ull p4p = fmul2(p3p[j4 >> 1], (j4 & 1) ? s3p : c3p);
        const float2 vA = unpack2(fmul2(p4p, c4p));
        const float2 vB = unpack2(fmul2(p4p, s4p));
        const ull sA0 = pack2(vA.x), sA1 = pack2(vA.y);
        const ull sB0 = pack2(vB.x), sB1 = pack2(vB.y);
        const ulonglong2* rA = reinterpret_cast<const ulonglong2*>(&Wsh[2 * j4][hoff]);
        const ulonglong2* rB = reinterpret_cast<const ulonglong2*>(&Wsh[2 * j4 + 1][hoff]);
        {
            const ulonglong2 w0 = rA[0], w1 = rA[1], w2 = rA[2], w3 = rA[3];
            a0[0] = ffma2(w0.x, sA0, a0[0]); a0[1] = ffma2(w0.y, sA0, a0[1]);
            a0[2] = ffma2(w1.x, sA0, a0[2]); a0[3] = ffma2(w1.y, sA0, a0[3]);
            a0[4] = ffma2(w2.x, sA0, a0[4]); a0[5] = ffma2(w2.y, sA0, a0[5]);
            a0[6] = ffma2(w3.x, sA0, a0[6]); a0[7] = ffma2(w3.y, sA0, a0[7]);
            a1[0] = ffma2(w0.x, sA1, a1[0]); a1[1] = ffma2(w0.y, sA1, a1[1]);
            a1[2] = ffma2(w1.x, sA1, a1[2]); a1[3] = ffma2(w1.y, sA1, a1[3]);
            a1[4] = ffma2(w2.x, sA1, a1[4]); a1[5] = ffma2(w2.y, sA1, a1[5]);
            a1[6] = ffma2(w3.x, sA1, a1[6]); a1[7] = ffma2(w3.y, sA1, a1[7]);
        }
        {
            const ulonglong2 w0 = rB[0], w1 = rB[1], w2 = rB[2], w3 = rB[3];
            a0[0] = ffma2(w0.x, sB0, a0[0]); a0[1] = ffma2(w0.y, sB0, a0[1]);
            a0[2] = ffma2(w1.x, sB0, a0[2]); a0[3] = ffma2(w1.y, sB0, a0[3]);
            a0[4] = ffma2(w2.x, sB0, a0[4]); a0[5] = ffma2(w2.y, sB0, a0[5]);
            a0[6] = ffma2(w3.x, sB0, a0[6]); a0[7] = ffma2(w3.y, sB0, a0[7]);
            a1[0] = ffma2(w0.x, sB1, a1[0]); a1[1] = ffma2(w0.y, sB1, a1[1]);
            a1[2] = ffma2(w1.x, sB1, a1[2]); a1[3] = ffma2(w1.y, sB1, a1[3]);
            a1[4] = ffma2(w2.x, sB1, a1[4]); a1[5] = ffma2(w2.y, sB1, a1[5]);
            a1[6] = ffma2(w3.x, sB1, a1[6]); a1[7] = ffma2(w3.y, sB1, a1[7]);
        }
    }

    // epilogue: this thread covers outputs 8h..8h+7 of its two elements;
    // max over all 16 outputs combined with partner lane via shfl.xor(1).
    #pragma unroll
    for (int e = 0; e < 2; ++e) {
        const ull* a = e ? a1 : a0;
        const int b = e ? b1 : b0;
        float pr[8];
        float mx = 0.0f;
        #pragma unroll
        for (int k = 0; k < 4; ++k) {
            const float2 re = unpack2(a[k]);       // outputs 8h+2k, 8h+2k+1
            const float2 im = unpack2(a[4 + k]);
            pr[2 * k + 0] = re.x * re.x + im.x * im.x;
            pr[2 * k + 1] = re.y * re.y + im.y * im.y;
            mx = fmaxf(mx, fmaxf(pr[2 * k], pr[2 * k + 1]));
        }
        mx = fmaxf(mx, __shfl_xor_sync(0xffffffffu, mx, 1));
        const float inv = 1.0f / mx;
        float4* ov = reinterpret_cast<float4*>(out + (size_t)b * (G * NOUT) + gsel * NOUT + 8 * h);
        #pragma unroll
        for (int i4 = 0; i4 < 2; ++i4) {
            float4 o;
            o.x = pr[i4 * 4 + 0] * inv;
            o.y = pr[i4 * 4 + 1] * inv;
            o.z = pr[i4 * 4 + 2] * inv;
            o.w = pr[i4 * 4 + 3] * inv;
            ov[i4] = o;
        }
    }
}

extern "C" void kernel_launch(void* const* d_in, const int* in_sizes, int n_in,
                              void* d_out, int out_size) {
    const float* x = (const float*)d_in[0];        // [B, 5]
    const float* w = (const float*)d_in[1];        // [4, 4, 5, 3]
    float* out = (float*)d_out;                    // [B, 64]
    const int B = in_sizes[0] / NQ;

    build_unitaries_kernel<<<G, 512>>>(w);
    const int tiles = (B + 127) / 128;             // 128 elements per tile
    qgen_main_kernel<<<tiles * G, 128>>>(x, out, B);
}

// round 12
// speedup vs baseline: 1.2766x; 1.0182x over previous
#include <cuda_runtime.h>
#include <cuda_bf16.h>
#include <math.h>

// ---------------------------------------------------------------------------
// PatchQuantumGenerator: 5 qubits, 1 ancilla, 4 StronglyEntanglingLayers,
// 4 generators.
//   * circuit after RY-embedding = fixed 32x32 unitary U_g per generator
//   * embedded state is a real product state s[j]
//   * p0/max(p0) == probs[:16]/max(probs[:16])  (sum normalization cancels)
// => out[b, g*16+i] = |y_i|^2 / max_i |y_i|^2,  y = U_g[0:16,:] @ s(b)
// Kernel B: packed fp32x2 FMA, 2 elems/thread, output columns split across
// thread pairs. PDL overlaps kernel A with kernel B's prologue.
// ---------------------------------------------------------------------------

#define NQ 5
#define DIM 32
#define NOUT 16
#define G 4
#define L 4
#define NGATES (L * NQ)

// W layout per row j: [Re(0..7), Im(0..7), Re(8..15), Im(8..15)]
// -> half h occupies floats [16h, 16h+16): its 8 Re then its 8 Im.
__device__ float g_W[G][DIM][2 * NOUT];

typedef unsigned long long ull;

__device__ __forceinline__ ull ffma2(ull a, ull b, ull c) {
    ull d;
    asm("fma.rn.f32x2 %0, %1, %2, %3;" : "=l"(d) : "l"(a), "l"(b), "l"(c));
    return d;
}
__device__ __forceinline__ ull fmul2(ull a, ull b) {
    ull d;
    asm("mul.rn.f32x2 %0, %1, %2;" : "=l"(d) : "l"(a), "l"(b));
    return d;
}
__device__ __forceinline__ ull packab(float lo, float hi) {
    ull r;
    asm("mov.b64 %0, {%1, %2};" : "=l"(r) : "f"(lo), "f"(hi));
    return r;
}
__device__ __forceinline__ ull pack2(float x) {
    ull r;
    asm("mov.b64 %0, {%1, %1};" : "=l"(r) : "f"(x));
    return r;
}
__device__ __forceinline__ float2 unpack2(ull a) {
    float lo, hi;
    asm("mov.b64 {%0, %1}, %2;" : "=f"(lo), "=f"(hi) : "l"(a));
    return make_float2(lo, hi);
}

// ---------------------------------------------------------------------------
// Kernel A: build the 4 unitaries. One block per generator, 512 threads:
// thread = (col = t>>4, p = t&15); per-gate sync is warp-local.
// Ends with a PDL trigger so kernel B can launch while A drains.
// ---------------------------------------------------------------------------
__global__ void __launch_bounds__(512, 1)
build_unitaries_kernel(const float* __restrict__ w) {
    __shared__ float2 S[DIM][DIM];        // [column][amplitude], 8KB
    __shared__ float gm[NGATES][8];       // gate matrices

    const int g   = blockIdx.x;
    const int t   = threadIdx.x;          // 0..511
    const int col = t >> 4;               // 0..31
    const int p   = t & 15;               // pair index 0..15

    if (t < NGATES) {
        const int l = t / NQ, q = t % NQ;
        const float phi   = w[((g * L + l) * NQ + q) * 3 + 0];
        const float theta = w[((g * L + l) * NQ + q) * 3 + 1];
        const float omega = w[((g * L + l) * NQ + q) * 3 + 2];
        const float c = cosf(0.5f * theta);
        const float s = sinf(0.5f * theta);
        float epx, epy, emx, emy;
        sincosf(-0.5f * (phi + omega), &epy, &epx);   // ep = e^{-i(phi+omega)/2}
        sincosf(-0.5f * (phi - omega), &emy, &emx);   // em = e^{-i(phi-omega)/2}
        // m00 = ep*c ; m01 = -conj(em)*s ; m10 = em*s ; m11 = conj(ep)*c
        gm[t][0] = epx * c;   gm[t][1] = epy * c;
        gm[t][2] = -emx * s;  gm[t][3] = emy * s;
        gm[t][4] = emx * s;   gm[t][5] = emy * s;
        gm[t][6] = epx * c;   gm[t][7] = -epy * c;
    }

    S[col][p]      = make_float2(col == p      ? 1.0f : 0.0f, 0.0f);
    S[col][p + 16] = make_float2(col == p + 16 ? 1.0f : 0.0f, 0.0f);
    __syncthreads();

    float2* a = S[col];

    for (int l = 0; l < L; ++l) {
        for (int q = 0; q < NQ; ++q) {
            const float* m = gm[l * NQ + q];
            const int msk = 1 << (4 - q);
            const int lo  = p & (msk - 1);
            const int i0  = ((p & ~(msk - 1)) << 1) | lo;
            const int i1  = i0 | msk;
            const float2 a0 = a[i0], a1 = a[i1];
            float2 n0, n1;
            n0.x = m[0] * a0.x - m[1] * a0.y + m[2] * a1.x - m[3] * a1.y;
            n0.y = m[0] * a0.y + m[1] * a0.x + m[2] * a1.y + m[3] * a1.x;
            n1.x = m[4] * a0.x - m[5] * a0.y + m[6] * a1.x - m[7] * a1.y;
            n1.y = m[4] * a0.y + m[5] * a0.x + m[6] * a1.y + m[7] * a1.x;
            a[i0] = n0;
            a[i1] = n1;
            __syncwarp();
        }
        const int r = (l % (NQ - 1)) + 1;
        for (int q = 0; q < NQ; ++q) {
            const int cm = 1 << (4 - q);
            const int tq = (q + r) % NQ;
            const int tm = 1 << (4 - tq);
            const int lo = p & (tm - 1);
            const int i0 = ((p & ~(tm - 1)) << 1) | lo;   // target bit = 0
            if (i0 & cm) {
                const int i1 = i0 | tm;
                const float2 tmp = a[i0];
                a[i0] = a[i1];
                a[i1] = tmp;
            }
            __syncwarp();
        }
    }

    // output i = p: Re -> col (i>>3)*16 + (i&7), Im -> +8
    const int h  = p >> 3;
    const int i7 = p & 7;
    g_W[g][col][h * 16 + i7]     = a[p].x;
    g_W[g][col][h * 16 + 8 + i7] = a[p].y;

    __threadfence();
#if __CUDA_ARCH__ >= 900
    cudaTriggerProgrammaticLaunchCompletion();
#endif
}

// ---------------------------------------------------------------------------
// Kernel B: block = (tile of 128 batch elems) x (one g). 128 threads.
// Thread = (idx = tid>>1 -> elems b0,b0+64 ; h = tid&1 -> col half).
// Prologue (x load + sincos + packed prefix) runs BEFORE the PDL grid
// dependency sync; g_W is read only after it.
// ---------------------------------------------------------------------------
__global__ void __launch_bounds__(128, 6)
qgen_main_kernel(const float* __restrict__ x, float* __restrict__ out, int B) {
    __shared__ float Wsh[DIM][2 * NOUT];   // 4 KB
    const int gsel = blockIdx.x & 3;
    const int tile = blockIdx.x >> 2;

    const int h   = threadIdx.x & 1;       // column half
    const int idx = threadIdx.x >> 1;      // 0..63
    const int b0r = tile * 128 + idx;
    const int b1r = b0r + 64;
    // clamp for the (never-taken in practice) tail; all threads stay alive
    const int b0 = min(b0r, B - 1);
    const int b1 = min(b1r, B - 1);

    // ---- prologue: packed (elem0, elem1) product-state prefix ----
    ull p3p[8], c3p, s3p, c4p, s4p;
    {
        float cc0[NQ], ss0[NQ], cc1[NQ], ss1[NQ];
        #pragma unroll
        for (int q = 0; q < NQ; ++q) {
            __sincosf(0.5f * x[b0 * NQ + q], &ss0[q], &cc0[q]);
            __sincosf(0.5f * x[b1 * NQ + q], &ss1[q], &cc1[q]);
        }
        ull f0c = packab(cc0[0], cc1[0]), f0s = packab(ss0[0], ss1[0]);
        ull f1c = packab(cc0[1], cc1[1]), f1s = packab(ss0[1], ss1[1]);
        ull f2c = packab(cc0[2], cc1[2]), f2s = packab(ss0[2], ss1[2]);
        c3p = packab(cc0[3], cc1[3]);  s3p = packab(ss0[3], ss1[3]);
        c4p = packab(cc0[4], cc1[4]);  s4p = packab(ss0[4], ss1[4]);
        ull p2p[4];
        p2p[0] = fmul2(f0c, f1c); p2p[1] = fmul2(f0c, f1s);
        p2p[2] = fmul2(f0s, f1c); p2p[3] = fmul2(f0s, f1s);
        #pragma unroll
        for (int k = 0; k < 4; ++k) {
            p3p[2 * k + 0] = fmul2(p2p[k], f2c);
            p3p[2 * k + 1] = fmul2(p2p[k], f2s);
        }
    }

    // ---- wait for kernel A's g_W, then stage it (all threads) ----
#if __CUDA_ARCH__ >= 900
    cudaGridDependencySynchronize();
#endif
    {
        // 4 KB = 256 float4; 128 threads -> 2 each
        const float4* src = reinterpret_cast<const float4*>(&g_W[gsel][0][0]);
        float4* dst = reinterpret_cast<float4*>(&Wsh[0][0]);
        dst[threadIdx.x]       = src[threadIdx.x];
        dst[threadIdx.x + 128] = src[threadIdx.x + 128];
    }
    __syncthreads();

    // acc layout (per element, this col-half): k<4 Re pairs, k>=4 Im pairs
    ull a0[8], a1[8];
    #pragma unroll
    for (int k = 0; k < 8; ++k) { a0[k] = 0ULL; a1[k] = 0ULL; }

    const int hoff = h * 16;   // float offset of this half within a row

    #pragma unroll
    for (int j4 = 0; j4 < 16; ++j4) {
        // p4 = p3[j4>>1] * (j4&1 ? s3 : c3); vA = p4*c4, vB = p4*s4 (packed)
        const ull p4p = fmul2(p3p[j4 >> 1], (j4 & 1) ? s3p : c3p);
        const float2 vA = unpack2(fmul2(p4p, c4p));
        const float2 vB = unpack2(fmul2(p4p, s4p));
        const ull sA0 = pack2(vA.x), sA1 = pack2(vA.y);
        const ull sB0 = pack2(vB.x), sB1 = pack2(vB.y);
        const ulonglong2* rA = reinterpret_cast<const ulonglong2*>(&Wsh[2 * j4][hoff]);
        const ulonglong2* rB = reinterpret_cast<const ulonglong2*>(&Wsh[2 * j4 + 1][hoff]);
        {
            const ulonglong2 w0 = rA[0], w1 = rA[1], w2 = rA[2], w3 = rA[3];
            a0[0] = ffma2(w0.x, sA0, a0[0]); a0[1] = ffma2(w0.y, sA0, a0[1]);
            a0[2] = ffma2(w1.x, sA0, a0[2]); a0[3] = ffma2(w1.y, sA0, a0[3]);
            a0[4] = ffma2(w2.x, sA0, a0[4]); a0[5] = ffma2(w2.y, sA0, a0[5]);
            a0[6] = ffma2(w3.x, sA0, a0[6]); a0[7] = ffma2(w3.y, sA0, a0[7]);
            a1[0] = ffma2(w0.x, sA1, a1[0]); a1[1] = ffma2(w0.y, sA1, a1[1]);
            a1[2] = ffma2(w1.x, sA1, a1[2]); a1[3] = ffma2(w1.y, sA1, a1[3]);
            a1[4] = ffma2(w2.x, sA1, a1[4]); a1[5] = ffma2(w2.y, sA1, a1[5]);
            a1[6] = ffma2(w3.x, sA1, a1[6]); a1[7] = ffma2(w3.y, sA1, a1[7]);
        }
        {
            const ulonglong2 w0 = rB[0], w1 = rB[1], w2 = rB[2], w3 = rB[3];
            a0[0] = ffma2(w0.x, sB0, a0[0]); a0[1] = ffma2(w0.y, sB0, a0[1]);
            a0[2] = ffma2(w1.x, sB0, a0[2]); a0[3] = ffma2(w1.y, sB0, a0[3]);
            a0[4] = ffma2(w2.x, sB0, a0[4]); a0[5] = ffma2(w2.y, sB0, a0[5]);
            a0[6] = ffma2(w3.x, sB0, a0[6]); a0[7] = ffma2(w3.y, sB0, a0[7]);
            a1[0] = ffma2(w0.x, sB1, a1[0]); a1[1] = ffma2(w0.y, sB1, a1[1]);
            a1[2] = ffma2(w1.x, sB1, a1[2]); a1[3] = ffma2(w1.y, sB1, a1[3]);
            a1[4] = ffma2(w2.x, sB1, a1[4]); a1[5] = ffma2(w2.y, sB1, a1[5]);
            a1[6] = ffma2(w3.x, sB1, a1[6]); a1[7] = ffma2(w3.y, sB1, a1[7]);
        }
    }

    // epilogue: outputs 8h..8h+7 per element; max combined via shfl.xor(1).
    #pragma unroll
    for (int e = 0; e < 2; ++e) {
        const ull* a = e ? a1 : a0;
        const int br = e ? b1r : b0r;
        float pr[8];
        float mx = 0.0f;
        #pragma unroll
        for (int k = 0; k < 4; ++k) {
            const float2 re = unpack2(a[k]);       // outputs 8h+2k, 8h+2k+1
            const float2 im = unpack2(a[4 + k]);
            pr[2 * k + 0] = re.x * re.x + im.x * im.x;
            pr[2 * k + 1] = re.y * re.y + im.y * im.y;
            mx = fmaxf(mx, fmaxf(pr[2 * k], pr[2 * k + 1]));
        }
        mx = fmaxf(mx, __shfl_xor_sync(0xffffffffu, mx, 1));
        const float inv = 1.0f / mx;
        if (br < B) {
            float4* ov = reinterpret_cast<float4*>(out + (size_t)br * (G * NOUT) + gsel * NOUT + 8 * h);
            #pragma unroll
            for (int i4 = 0; i4 < 2; ++i4) {
                float4 o;
                o.x = pr[i4 * 4 + 0] * inv;
                o.y = pr[i4 * 4 + 1] * inv;
                o.z = pr[i4 * 4 + 2] * inv;
                o.w = pr[i4 * 4 + 3] * inv;
                ov[i4] = o;
            }
        }
    }
}

extern "C" void kernel_launch(void* const* d_in, const int* in_sizes, int n_in,
                              void* d_out, int out_size) {
    const float* x = (const float*)d_in[0];        // [B, 5]
    const float* w = (const float*)d_in[1];        // [4, 4, 5, 3]
    float* out = (float*)d_out;                    // [B, 64]
    const int B = in_sizes[0] / NQ;

    build_unitaries_kernel<<<G, 512>>>(w);

    const int tiles = (B + 127) / 128;             // 128 elements per tile

    cudaLaunchConfig_t cfg = {};
    cfg.gridDim  = dim3(tiles * G);
    cfg.blockDim = dim3(128);
    cfg.dynamicSmemBytes = 0;
    cfg.stream = 0;
    cudaLaunchAttribute attr[1];
    attr[0].id = cudaLaunchAttributeProgrammaticStreamSerialization;
    attr[0].val.programmaticStreamSerializationAllowed = 1;
    cfg.attrs = attr;
    cfg.numAttrs = 1;
    cudaLaunchKernelEx(&cfg, qgen_main_kernel, x, out, B);
}